// round 1
// baseline (speedup 1.0000x reference)
#include <cuda_runtime.h>
#include <math.h>

#define B 8
#define C 256
#define H 128
#define W 128
#define OH 65
#define OW 65
#define HW (H*W)          // 16384
#define OHW (OH*OW)       // 4225
#define CPT 8             // channels per thread in gather kernel
#define CG (C/CPT)        // 32 channel groups

// Scratch: device globals (no allocation allowed)
__device__ float g_norm[B*H*W];          // 512 KB
__device__ float g_wts[B*OH*OW*9];       // ~1.22 MB, layout [b][oy][ox][9]

// ---------------------------------------------------------------------------
// Kernel 1: channel-wise L2 norm  n[b,h,w] = sqrt(sum_c x[b,c,h,w]^2)
// grid = B*H blocks, 128 threads (one per w). Coalesced across w per channel.
// ---------------------------------------------------------------------------
__global__ __launch_bounds__(128) void norm_kernel(const float* __restrict__ x) {
    int w  = threadIdx.x;          // 0..127
    int bh = blockIdx.x;           // 0..B*H-1
    int b  = bh >> 7;
    int h  = bh & 127;
    const float* p = x + (size_t)b * C * HW + (size_t)h * W + w;

    float s0 = 0.f, s1 = 0.f, s2 = 0.f, s3 = 0.f;
    #pragma unroll 4
    for (int c = 0; c < C; c += 4) {
        float a0 = p[(size_t)(c + 0) * HW];
        float a1 = p[(size_t)(c + 1) * HW];
        float a2 = p[(size_t)(c + 2) * HW];
        float a3 = p[(size_t)(c + 3) * HW];
        s0 = fmaf(a0, a0, s0);
        s1 = fmaf(a1, a1, s1);
        s2 = fmaf(a2, a2, s2);
        s3 = fmaf(a3, a3, s3);
    }
    g_norm[bh * W + w] = sqrtf((s0 + s1) + (s2 + s3));
}

// ---------------------------------------------------------------------------
// Kernel 2: softmax weights over the 3x3 window of norms (zero-padded).
// One thread per output pixel. wts layout [b][oy][ox][9].
// ---------------------------------------------------------------------------
__global__ __launch_bounds__(256) void wts_kernel() {
    int idx = blockIdx.x * blockDim.x + threadIdx.x;
    if (idx >= B * OHW) return;
    int ox = idx % OW;
    int t  = idx / OW;
    int oy = t % OH;
    int b  = t / OH;

    int iy0 = 2 * oy - 2;
    int ix0 = 2 * ox - 2;

    float v[9];
    #pragma unroll
    for (int i = 0; i < 3; i++) {
        int iy = iy0 + i;
        bool rok = (unsigned)iy < (unsigned)H;
        #pragma unroll
        for (int j = 0; j < 3; j++) {
            int ix = ix0 + j;
            bool ok = rok && ((unsigned)ix < (unsigned)W);
            v[i * 3 + j] = ok ? g_norm[(b * H + iy) * W + ix] : 0.f;
        }
    }

    float m = v[0];
    #pragma unroll
    for (int k = 1; k < 9; k++) m = fmaxf(m, v[k]);

    float e[9];
    float sum = 0.f;
    #pragma unroll
    for (int k = 0; k < 9; k++) {
        e[k] = expf(v[k] - m);
        sum += e[k];
    }
    float inv = 1.f / sum;

    float* wp = g_wts + (size_t)idx * 9;
    #pragma unroll
    for (int k = 0; k < 9; k++) wp[k] = e[k] * inv;
}

// ---------------------------------------------------------------------------
// Kernel 3: weighted gather. Thread = (b, cg, oy, ox), handles CPT channels.
// Weights loaded once per thread (amortized over CPT channels).
// ---------------------------------------------------------------------------
__global__ __launch_bounds__(256) void gather_kernel(const float* __restrict__ x,
                                                     float* __restrict__ out) {
    int idx = blockIdx.x * blockDim.x + threadIdx.x;   // exactly B*CG*OHW threads
    int ox = idx % OW;
    int t  = idx / OW;
    int oy = t % OH;
    t      = t / OH;
    int cg = t % CG;
    int b  = t / CG;

    const float* wp = g_wts + ((size_t)(b * OH + oy) * OW + ox) * 9;
    float wv[9];
    #pragma unroll
    for (int k = 0; k < 9; k++) wv[k] = wp[k];

    int iy0 = 2 * oy - 2;
    int ix0 = 2 * ox - 2;

    float acc[CPT];
    #pragma unroll
    for (int k = 0; k < CPT; k++) acc[k] = 0.f;

    const float* xb = x + (size_t)(b * C + cg * CPT) * HW;

    #pragma unroll
    for (int i = 0; i < 3; i++) {
        int iy = iy0 + i;
        if ((unsigned)iy >= (unsigned)H) continue;
        #pragma unroll
        for (int j = 0; j < 3; j++) {
            int ix = ix0 + j;
            if ((unsigned)ix >= (unsigned)W) continue;
            float w9 = wv[i * 3 + j];
            const float* p = xb + iy * W + ix;
            #pragma unroll
            for (int k = 0; k < CPT; k++) {
                acc[k] = fmaf(w9, p[(size_t)k * HW], acc[k]);
            }
        }
    }

    float* op = out + ((size_t)(b * C + cg * CPT) * OH + oy) * OW + ox;
    #pragma unroll
    for (int k = 0; k < CPT; k++) op[(size_t)k * OHW] = acc[k];
}

// ---------------------------------------------------------------------------
extern "C" void kernel_launch(void* const* d_in, const int* in_sizes, int n_in,
                              void* d_out, int out_size) {
    const float* x = (const float*)d_in[0];
    float* out = (float*)d_out;

    // K1: norms
    norm_kernel<<<B * H, 128>>>(x);

    // K2: softmax weights
    int n2 = B * OHW;
    wts_kernel<<<(n2 + 255) / 256, 256>>>();

    // K3: weighted gather
    int n3 = B * CG * OHW;   // 1,081,600 = 4225 blocks * 256
    gather_kernel<<<(n3 + 255) / 256, 256>>>(x, out);
}

// round 2
// speedup vs baseline: 1.0326x; 1.0326x over previous
#include <cuda_runtime.h>
#include <math.h>

#define B 8
#define C 256
#define H 128
#define W 128
#define OH 65
#define OW 65
#define HW (H*W)          // 16384
#define OHW (OH*OW)       // 4225
#define NPIX (B*OHW)      // 33800 output pixels
#define CPT 8             // channels per thread in gather kernel
#define CG (C/CPT)        // 32 channel groups
#define SPLIT 8           // channel splits in norm kernel
#define CPS (C/SPLIT)     // 32 channels per split

// Scratch: device globals (no allocation allowed)
__device__ float g_part[SPLIT*B*HW];     // 4 MB, partial sum-of-squares
__device__ float g_norm[B*HW];           // 512 KB
__device__ float g_wts[9*NPIX];          // ~1.22 MB, layout [k][b][oy][ox]

// ---------------------------------------------------------------------------
// Kernel 1: partial channel sum-of-squares, float4 loads, 8-way channel split.
// grid = (B*H/4, SPLIT), block = 128 (32 float4-lanes x 4 rows).
// ---------------------------------------------------------------------------
__global__ __launch_bounds__(128) void norm_part_kernel(const float* __restrict__ x) {
    int t   = threadIdx.x;
    int w4  = t & 31;            // float4 index in row (32 per row)
    int hl  = t >> 5;            // local row 0..3
    int bh4 = blockIdx.x;        // 0..B*H/4-1
    int b   = bh4 >> 5;          // H/4 = 32 row-groups per b
    int h   = ((bh4 & 31) << 2) + hl;
    int c0  = blockIdx.y * CPS;

    const float4* p = (const float4*)(x + ((size_t)(b * C + c0)) * HW + (size_t)h * W) + w4;

    float sx = 0.f, sy = 0.f, sz = 0.f, sw = 0.f;
    #pragma unroll 8
    for (int c = 0; c < CPS; c++) {
        float4 v = p[(size_t)c * (HW / 4)];
        sx = fmaf(v.x, v.x, sx);
        sy = fmaf(v.y, v.y, sy);
        sz = fmaf(v.z, v.z, sz);
        sw = fmaf(v.w, v.w, sw);
    }

    float4 o = make_float4(sx, sy, sz, sw);
    ((float4*)g_part)[(size_t)blockIdx.y * (B * HW / 4) + ((size_t)(b * H + h) * W) / 4 + w4] = o;
}

// ---------------------------------------------------------------------------
// Kernel 2: reduce 8 partials + sqrt -> g_norm. float4 granularity.
// ---------------------------------------------------------------------------
__global__ __launch_bounds__(256) void norm_reduce_kernel() {
    int i = blockIdx.x * blockDim.x + threadIdx.x;   // 0..B*HW/4-1
    if (i >= B * HW / 4) return;
    const float4* p = (const float4*)g_part;
    float4 a = p[i];
    #pragma unroll
    for (int s = 1; s < SPLIT; s++) {
        float4 v = p[(size_t)s * (B * HW / 4) + i];
        a.x += v.x; a.y += v.y; a.z += v.z; a.w += v.w;
    }
    a.x = sqrtf(a.x); a.y = sqrtf(a.y); a.z = sqrtf(a.z); a.w = sqrtf(a.w);
    ((float4*)g_norm)[i] = a;
}

// ---------------------------------------------------------------------------
// Kernel 3: softmax weights over 3x3 window of norms (zero-padded).
// wts layout transposed: [k][pixel] for coalesced gather-side loads.
// ---------------------------------------------------------------------------
__global__ __launch_bounds__(256) void wts_kernel() {
    int idx = blockIdx.x * blockDim.x + threadIdx.x;
    if (idx >= NPIX) return;
    int ox = idx % OW;
    int t  = idx / OW;
    int oy = t % OH;
    int b  = t / OH;

    int iy0 = 2 * oy - 2;
    int ix0 = 2 * ox - 2;

    float v[9];
    #pragma unroll
    for (int i = 0; i < 3; i++) {
        int iy = iy0 + i;
        bool rok = (unsigned)iy < (unsigned)H;
        #pragma unroll
        for (int j = 0; j < 3; j++) {
            int ix = ix0 + j;
            bool ok = rok && ((unsigned)ix < (unsigned)W);
            v[i * 3 + j] = ok ? g_norm[(b * H + iy) * W + ix] : 0.f;
        }
    }

    float m = v[0];
    #pragma unroll
    for (int k = 1; k < 9; k++) m = fmaxf(m, v[k]);

    float e[9];
    float sum = 0.f;
    #pragma unroll
    for (int k = 0; k < 9; k++) {
        e[k] = expf(v[k] - m);
        sum += e[k];
    }
    float inv = 1.f / sum;

    #pragma unroll
    for (int k = 0; k < 9; k++) g_wts[k * NPIX + idx] = e[k] * inv;
}

// ---------------------------------------------------------------------------
// Kernel 4: weighted gather. Thread = (b, cg, oy, ox), CPT channels each.
// Grid traversed in REVERSE so the gather consumes the tail of the norm
// kernel's L2 residue of x first (x=134MB vs L2=126MB).
// ---------------------------------------------------------------------------
__global__ __launch_bounds__(256) void gather_kernel(const float* __restrict__ x,
                                                     float* __restrict__ out) {
    int lin = blockIdx.x * blockDim.x + threadIdx.x;
    int idx = (B * CG * OHW - 1) - lin;              // reversed traversal

    int ox = idx % OW;
    int t  = idx / OW;
    int oy = t % OH;
    t      = t / OH;
    int cg = t % CG;
    int b  = t / CG;

    int pix = (b * OH + oy) * OW + ox;
    float wv[9];
    #pragma unroll
    for (int k = 0; k < 9; k++) wv[k] = g_wts[k * NPIX + pix];

    int iy0 = 2 * oy - 2;
    int ix0 = 2 * ox - 2;

    float acc[CPT];
    #pragma unroll
    for (int k = 0; k < CPT; k++) acc[k] = 0.f;

    const float* xb = x + (size_t)(b * C + cg * CPT) * HW;

    #pragma unroll
    for (int i = 0; i < 3; i++) {
        int iy = iy0 + i;
        if ((unsigned)iy >= (unsigned)H) continue;
        #pragma unroll
        for (int j = 0; j < 3; j++) {
            int ix = ix0 + j;
            if ((unsigned)ix >= (unsigned)W) continue;
            float w9 = wv[i * 3 + j];
            const float* p = xb + iy * W + ix;
            #pragma unroll
            for (int k = 0; k < CPT; k++) {
                acc[k] = fmaf(w9, p[(size_t)k * HW], acc[k]);
            }
        }
    }

    float* op = out + ((size_t)(b * C + cg * CPT) * OH + oy) * OW + ox;
    #pragma unroll
    for (int k = 0; k < CPT; k++) op[(size_t)k * OHW] = acc[k];
}

// ---------------------------------------------------------------------------
extern "C" void kernel_launch(void* const* d_in, const int* in_sizes, int n_in,
                              void* d_out, int out_size) {
    const float* x = (const float*)d_in[0];
    float* out = (float*)d_out;

    // K1: partial sum-of-squares (8-way channel split, float4)
    dim3 g1(B * H / 4, SPLIT);
    norm_part_kernel<<<g1, 128>>>(x);

    // K2: reduce partials + sqrt
    int n2 = B * HW / 4;
    norm_reduce_kernel<<<(n2 + 255) / 256, 256>>>();

    // K3: softmax weights
    wts_kernel<<<(NPIX + 255) / 256, 256>>>();

    // K4: weighted gather (reversed order)
    int n4 = B * CG * OHW;   // 1,081,600 = 4225 blocks * 256
    gather_kernel<<<n4 / 256, 256>>>(x, out);
}

// round 3
// speedup vs baseline: 1.0768x; 1.0429x over previous
#include <cuda_runtime.h>
#include <math.h>

#define B 8
#define C 256
#define H 128
#define W 128
#define OH 65
#define OW 65
#define HW (H*W)          // 16384
#define OHW (OH*OW)       // 4225
#define NPIX (B*OHW)      // 33800 output pixels
#define CPT 8             // channels per thread in gather kernel
#define CG (C/CPT)        // 32 channel groups
#define SPLIT 8           // channel splits in norm kernel
#define CPS (C/SPLIT)     // 32 channels per split

// Scratch: device globals (no allocation allowed)
__device__ float g_part[SPLIT*B*HW];     // 4 MB, partial sum-of-squares
__device__ float g_norm[B*HW];           // 512 KB
__device__ float g_wts[9*NPIX];          // ~1.22 MB, layout [k][b][oy][ox]

// ---------------------------------------------------------------------------
// Kernel 1: partial channel sum-of-squares, float4 loads, 8-way channel split.
// ---------------------------------------------------------------------------
__global__ __launch_bounds__(128) void norm_part_kernel(const float* __restrict__ x) {
    int t   = threadIdx.x;
    int w4  = t & 31;            // float4 index in row (32 per row)
    int hl  = t >> 5;            // local row 0..3
    int bh4 = blockIdx.x;        // 0..B*H/4-1
    int b   = bh4 >> 5;          // H/4 = 32 row-groups per b
    int h   = ((bh4 & 31) << 2) + hl;
    int c0  = blockIdx.y * CPS;

    const float4* p = (const float4*)(x + ((size_t)(b * C + c0)) * HW + (size_t)h * W) + w4;

    float sx = 0.f, sy = 0.f, sz = 0.f, sw = 0.f;
    #pragma unroll 8
    for (int c = 0; c < CPS; c++) {
        float4 v = p[(size_t)c * (HW / 4)];
        sx = fmaf(v.x, v.x, sx);
        sy = fmaf(v.y, v.y, sy);
        sz = fmaf(v.z, v.z, sz);
        sw = fmaf(v.w, v.w, sw);
    }

    float4 o = make_float4(sx, sy, sz, sw);
    ((float4*)g_part)[(size_t)blockIdx.y * (B * HW / 4) + ((size_t)(b * H + h) * W) / 4 + w4] = o;
}

// ---------------------------------------------------------------------------
// Kernel 2: reduce partials + sqrt -> g_norm.
// ---------------------------------------------------------------------------
__global__ __launch_bounds__(256) void norm_reduce_kernel() {
    int i = blockIdx.x * blockDim.x + threadIdx.x;
    if (i >= B * HW / 4) return;
    const float4* p = (const float4*)g_part;
    float4 a = p[i];
    #pragma unroll
    for (int s = 1; s < SPLIT; s++) {
        float4 v = p[(size_t)s * (B * HW / 4) + i];
        a.x += v.x; a.y += v.y; a.z += v.z; a.w += v.w;
    }
    a.x = sqrtf(a.x); a.y = sqrtf(a.y); a.z = sqrtf(a.z); a.w = sqrtf(a.w);
    ((float4*)g_norm)[i] = a;
}

// ---------------------------------------------------------------------------
// Kernel 3: softmax weights over 3x3 window of norms (zero-padded).
// wts layout transposed: [k][pixel] for coalesced gather-side loads.
// ---------------------------------------------------------------------------
__global__ __launch_bounds__(256) void wts_kernel() {
    int idx = blockIdx.x * blockDim.x + threadIdx.x;
    if (idx >= NPIX) return;
    int ox = idx % OW;
    int t  = idx / OW;
    int oy = t % OH;
    int b  = t / OH;

    int iy0 = 2 * oy - 2;
    int ix0 = 2 * ox - 2;

    float v[9];
    #pragma unroll
    for (int i = 0; i < 3; i++) {
        int iy = iy0 + i;
        bool rok = (unsigned)iy < (unsigned)H;
        #pragma unroll
        for (int j = 0; j < 3; j++) {
            int ix = ix0 + j;
            bool ok = rok && ((unsigned)ix < (unsigned)W);
            v[i * 3 + j] = ok ? g_norm[(b * H + iy) * W + ix] : 0.f;
        }
    }

    float m = v[0];
    #pragma unroll
    for (int k = 1; k < 9; k++) m = fmaxf(m, v[k]);

    float e[9];
    float sum = 0.f;
    #pragma unroll
    for (int k = 0; k < 9; k++) {
        e[k] = expf(v[k] - m);
        sum += e[k];
    }
    float inv = 1.f / sum;

    #pragma unroll
    for (int k = 0; k < 9; k++) g_wts[k * NPIX + idx] = e[k] * inv;
}

// ---------------------------------------------------------------------------
// Kernel 4: weighted gather, branch-free (weight-zero + index-clamp at pads),
// float2+float loads per row per channel, loads front-batched per row.
// ---------------------------------------------------------------------------
__global__ __launch_bounds__(256) void gather_kernel(const float* __restrict__ x,
                                                     float* __restrict__ out) {
    int lin = blockIdx.x * blockDim.x + threadIdx.x;
    int idx = (B * CG * OHW - 1) - lin;              // reversed traversal (L2 residue)

    int ox = idx % OW;
    int t  = idx / OW;
    int oy = t % OH;
    t      = t / OH;
    int cg = t % CG;
    int b  = t / CG;

    int pix = (b * OH + oy) * OW + ox;
    float wv[9];
    #pragma unroll
    for (int k = 0; k < 9; k++) wv[k] = g_wts[k * NPIX + pix];

    // Column handling: float2 covers j=0,1 at base cb=2ox-2; scalar covers j=2 at cs=2ox.
    int cb = 2 * ox - 2;
    int cs = 2 * ox;
    if (ox == 0) {           // cols -2,-1 are padding
        cb = 0;
        wv[0] = 0.f; wv[1] = 0.f;
        wv[3] = 0.f; wv[4] = 0.f;
        wv[6] = 0.f; wv[7] = 0.f;
    }
    if (ox == OW - 1) {      // col 128 is padding
        cs = W - 1;
        wv[2] = 0.f; wv[5] = 0.f; wv[8] = 0.f;
    }

    // Row handling: clamp invalid rows, zero their weights.
    int iy0 = 2 * oy - 2;
    int iyv[3];
    #pragma unroll
    for (int i = 0; i < 3; i++) {
        int iy = iy0 + i;
        if (iy < 0)      { iy = 0;     wv[i*3+0] = wv[i*3+1] = wv[i*3+2] = 0.f; }
        else if (iy >= H){ iy = H - 1; wv[i*3+0] = wv[i*3+1] = wv[i*3+2] = 0.f; }
        iyv[i] = iy;
    }

    float acc[CPT];
    #pragma unroll
    for (int k = 0; k < CPT; k++) acc[k] = 0.f;

    const float* xb = x + (size_t)(b * C + cg * CPT) * HW;

    #pragma unroll
    for (int i = 0; i < 3; i++) {
        const float* rp = xb + iyv[i] * W;
        float2 d2[CPT];
        float  d1[CPT];
        #pragma unroll
        for (int k = 0; k < CPT; k++) {
            d2[k] = *(const float2*)(rp + (size_t)k * HW + cb);
            d1[k] = rp[(size_t)k * HW + cs];
        }
        float w0 = wv[i*3+0], w1 = wv[i*3+1], w2 = wv[i*3+2];
        #pragma unroll
        for (int k = 0; k < CPT; k++) {
            acc[k] = fmaf(w0, d2[k].x, acc[k]);
            acc[k] = fmaf(w1, d2[k].y, acc[k]);
            acc[k] = fmaf(w2, d1[k],   acc[k]);
        }
    }

    float* op = out + ((size_t)(b * C + cg * CPT) * OH + oy) * OW + ox;
    #pragma unroll
    for (int k = 0; k < CPT; k++) op[(size_t)k * OHW] = acc[k];
}

// ---------------------------------------------------------------------------
extern "C" void kernel_launch(void* const* d_in, const int* in_sizes, int n_in,
                              void* d_out, int out_size) {
    const float* x = (const float*)d_in[0];
    float* out = (float*)d_out;

    dim3 g1(B * H / 4, SPLIT);
    norm_part_kernel<<<g1, 128>>>(x);

    int n2 = B * HW / 4;
    norm_reduce_kernel<<<(n2 + 255) / 256, 256>>>();

    wts_kernel<<<(NPIX + 255) / 256, 256>>>();

    int n4 = B * CG * OHW;   // 1,081,600 = 4225 blocks * 256
    gather_kernel<<<n4 / 256, 256>>>(x, out);
}